// round 5
// baseline (speedup 1.0000x reference)
#include <cuda_runtime.h>
#include <cuda_fp16.h>
#include <cstdint>
#include <cstddef>

// ============================================================
// GAT attention head, N=8192, IN_F=128, OUT_F=64
//  h = X@W ; e = LeakyReLU(fs_i + fd_j) masked by adj ; softmax ; P@h ; elu
//
// Key identity (monotone exp + leakyrelu):
//   exp(LR(fs+fd)) = max( E_i*E_j , G_i*G_j ),
//   E = exp(f), G = exp(0.2 f)  -> no exp in the N^2 loop.
// Fixed-max softmax (logits bounded ~|7|) -> single pass, fp32 denominators,
// fp16 P/h through mma.sync.m16n8k16 with fp32 accumulators.
// ============================================================

#define NT 8192
#define IN_FEAT 128
#define OUT_FEAT 64
#define SPLITS 4
#define JSPAN (NT / SPLITS)      // 2048
#define JTILE 128
#define NTILES (JSPAN / JTILE)   // 16
#define HROW 272                 // padded smem row stride (bytes) -> conflict-free

// ---------------- scratch (static device arrays; no allocation) ----------
__device__ __half g_ht[OUT_FEAT * NT];          // h transposed fp16: [f][j]
__device__ float2 g_EGs[NT];                    // (exp(fsrc), exp(0.2 fsrc))
__device__ float2 g_EGd[NT];                    // (exp(fdst), exp(0.2 fdst))
__device__ float  g_num[SPLITS * NT * OUT_FEAT];// partial numerators
__device__ float  g_den[SPLITS * NT];           // partial denominators

// =========================================================================
// Kernel 1: h = X @ W ; f_src/f_dst = h . a-halves ; write h^T fp16 + EG tables
// one warp per node row; 8 rows per block.
// =========================================================================
__global__ void __launch_bounds__(256) prep_kernel(const float* __restrict__ x,
                                                   const float* __restrict__ W,
                                                   const float* __restrict__ a) {
    __shared__ float Ws[IN_FEAT * OUT_FEAT];  // 32 KB
    __shared__ float xs[8 * IN_FEAT];         // 4 KB
    int tid = threadIdx.x;
    int i0 = blockIdx.x * 8;

    for (int idx = tid; idx < IN_FEAT * OUT_FEAT; idx += 256) Ws[idx] = W[idx];
    for (int idx = tid; idx < 8 * IN_FEAT; idx += 256) xs[idx] = x[(size_t)i0 * IN_FEAT + idx];
    __syncthreads();

    int w = tid >> 5, l = tid & 31;
    float acc0 = 0.f, acc1 = 0.f;
#pragma unroll
    for (int k = 0; k < IN_FEAT; k++) {
        float xv = xs[w * IN_FEAT + k];
        float2 wv = *(const float2*)&Ws[k * OUT_FEAT + 2 * l];
        acc0 = fmaf(xv, wv.x, acc0);
        acc1 = fmaf(xv, wv.y, acc1);
    }
    int i = i0 + w;
    g_ht[(size_t)(2 * l) * NT + i]     = __float2half(acc0);
    g_ht[(size_t)(2 * l + 1) * NT + i] = __float2half(acc1);

    float a0 = a[2 * l], a1 = a[2 * l + 1];
    float a2 = a[OUT_FEAT + 2 * l], a3 = a[OUT_FEAT + 2 * l + 1];
    float s = acc0 * a0 + acc1 * a1;
    float d = acc0 * a2 + acc1 * a3;
#pragma unroll
    for (int off = 16; off; off >>= 1) {
        s += __shfl_xor_sync(0xFFFFFFFFu, s, off);
        d += __shfl_xor_sync(0xFFFFFFFFu, d, off);
    }
    if (l == 0) {
        g_EGs[i] = make_float2(expf(s), expf(0.2f * s));
        g_EGd[i] = make_float2(expf(d), expf(0.2f * d));
    }
}

// =========================================================================
// Kernel 2: fused masked-softmax attention, register-accumulated P@h (HMMA)
// grid (64 row-blocks, SPLITS j-splits), 256 threads, 2 CTAs/SM.
// Each warp: 16 output rows x 64 feats. P computed directly in A-frag layout.
// =========================================================================
__device__ __forceinline__ void mma16816(float* d, uint32_t a0, uint32_t a1,
                                         uint32_t a2, uint32_t a3,
                                         uint32_t b0, uint32_t b1) {
    asm volatile(
        "mma.sync.aligned.m16n8k16.row.col.f32.f16.f16.f32 "
        "{%0,%1,%2,%3}, {%4,%5,%6,%7}, {%8,%9}, {%0,%1,%2,%3};"
        : "+f"(d[0]), "+f"(d[1]), "+f"(d[2]), "+f"(d[3])
        : "r"(a0), "r"(a1), "r"(a2), "r"(a3), "r"(b0), "r"(b1));
}

__device__ __forceinline__ uint32_t packh2(float x, float y) {
    __half2 h = __floats2half2_rn(x, y);
    return *reinterpret_cast<uint32_t*>(&h);
}

__global__ void __launch_bounds__(256, 2) attn_kernel(const int* __restrict__ adj) {
    __shared__ __align__(16) char hbuf[2][OUT_FEAT * HROW];  // 2 x 17408 B

    int tid = threadIdx.x, w = tid >> 5, lane = tid & 31;
    int r = lane >> 2, q = lane & 3;
    int i0 = blockIdx.x * 128;
    int split = blockIdx.y;
    int jbase = split * JSPAN;

    int R0 = i0 + w * 16 + r;                 // this lane's two rows: R0, R0+8
    float2 egs0 = g_EGs[R0];
    float2 egs1 = g_EGs[R0 + 8];

    float acc[8][4];
#pragma unroll
    for (int nt = 0; nt < 8; nt++)
#pragma unroll
        for (int v = 0; v < 4; v++) acc[nt][v] = 0.f;
    float ds0 = 0.f, ds1 = 0.f;

    // H staging thread mapping: idx -> (f = idx>>4, c = idx&15); 16B chunk each
    int hf[4], hc[4];
#pragma unroll
    for (int u = 0; u < 4; u++) { int idx = tid + u * 256; hf[u] = idx >> 4; hc[u] = idx & 15; }

    // preload tile 0
    uint4 hreg[4];
#pragma unroll
    for (int u = 0; u < 4; u++)
        hreg[u] = *(const uint4*)&g_ht[(size_t)hf[u] * NT + jbase + hc[u] * 8];
#pragma unroll
    for (int u = 0; u < 4; u++)
        *(uint4*)&hbuf[0][hf[u] * HROW + hc[u] * 16] = hreg[u];
    __syncthreads();

    const size_t rowA = (size_t)R0 * NT;
    const size_t rowB = (size_t)(R0 + 8) * NT;

    for (int t = 0; t < NTILES; t++) {
        int b = t & 1;
        if (t + 1 < NTILES) {
            int jn = jbase + (t + 1) * JTILE;
#pragma unroll
            for (int u = 0; u < 4; u++)
                hreg[u] = *(const uint4*)&g_ht[(size_t)hf[u] * NT + jn + hc[u] * 8];
        }
        const char* hb = hbuf[b];
        int Jt = jbase + t * JTILE;

#pragma unroll
        for (int kk = 0; kk < 8; kk++) {
            int jc = Jt + kk * 16 + q * 2;
            int2 a00 = *(const int2*)&adj[rowA + jc];
            int2 a01 = *(const int2*)&adj[rowA + jc + 8];
            int2 a10 = *(const int2*)&adj[rowB + jc];
            int2 a11 = *(const int2*)&adj[rowB + jc + 8];
            float4 eg0 = *(const float4*)&g_EGd[jc];      // E(j),G(j),E(j+1),G(j+1)
            float4 eg1 = *(const float4*)&g_EGd[jc + 8];

            // p = adj ? max(E_i*E_j, G_i*G_j) : 0
            float p00 = a00.x ? fmaxf(egs0.x * eg0.x, egs0.y * eg0.y) : 0.f;
            float p01 = a00.y ? fmaxf(egs0.x * eg0.z, egs0.y * eg0.w) : 0.f;
            float p02 = a01.x ? fmaxf(egs0.x * eg1.x, egs0.y * eg1.y) : 0.f;
            float p03 = a01.y ? fmaxf(egs0.x * eg1.z, egs0.y * eg1.w) : 0.f;
            float p10 = a10.x ? fmaxf(egs1.x * eg0.x, egs1.y * eg0.y) : 0.f;
            float p11 = a10.y ? fmaxf(egs1.x * eg0.z, egs1.y * eg0.w) : 0.f;
            float p12 = a11.x ? fmaxf(egs1.x * eg1.x, egs1.y * eg1.y) : 0.f;
            float p13 = a11.y ? fmaxf(egs1.x * eg1.z, egs1.y * eg1.w) : 0.f;

            ds0 += (p00 + p01) + (p02 + p03);
            ds1 += (p10 + p11) + (p12 + p13);

            uint32_t A0 = packh2(p00, p01);   // (r,   c0/c0+1)
            uint32_t A1 = packh2(p10, p11);   // (r+8, c0/c0+1)
            uint32_t A2 = packh2(p02, p03);   // (r,   c0+8/+9)
            uint32_t A3 = packh2(p12, p13);   // (r+8, c0+8/+9)

            int ko = kk * 32 + q * 4;         // byte offset of k0 within H row
#pragma unroll
            for (int nt = 0; nt < 8; nt++) {
                const char* base = hb + (nt * 8 + r) * HROW;
                uint32_t b0 = *(const uint32_t*)(base + ko);       // (k0,k0+1, n)
                uint32_t b1 = *(const uint32_t*)(base + ko + 16);  // (k0+8,+9, n)
                mma16816(acc[nt], A0, A1, A2, A3, b0, b1);
            }
        }

        __syncthreads();
        if (t + 1 < NTILES) {
#pragma unroll
            for (int u = 0; u < 4; u++)
                *(uint4*)&hbuf[b ^ 1][hf[u] * HROW + hc[u] * 16] = hreg[u];
        }
        __syncthreads();
    }

    // denominator: reduce over the 4 lanes sharing a row (xor 1, 2)
    ds0 += __shfl_xor_sync(0xFFFFFFFFu, ds0, 1);
    ds0 += __shfl_xor_sync(0xFFFFFFFFu, ds0, 2);
    ds1 += __shfl_xor_sync(0xFFFFFFFFu, ds1, 1);
    ds1 += __shfl_xor_sync(0xFFFFFFFFu, ds1, 2);
    if (q == 0) {
        g_den[(size_t)split * NT + R0]     = ds0;
        g_den[(size_t)split * NT + R0 + 8] = ds1;
    }

    // numerators -> gmem partials
    float* gn = &g_num[(size_t)split * NT * OUT_FEAT];
#pragma unroll
    for (int nt = 0; nt < 8; nt++) {
        int col = nt * 8 + q * 2;
        *(float2*)&gn[(size_t)R0 * OUT_FEAT + col]       = make_float2(acc[nt][0], acc[nt][1]);
        *(float2*)&gn[(size_t)(R0 + 8) * OUT_FEAT + col] = make_float2(acc[nt][2], acc[nt][3]);
    }
}

// =========================================================================
// Kernel 3: combine split partials, divide, elu
// =========================================================================
__global__ void __launch_bounds__(256) finalize_kernel(float* __restrict__ out) {
    size_t idx = (size_t)blockIdx.x * 256 + threadIdx.x;
    size_t i = idx >> 6;
    float num = 0.f, den = 0.f;
#pragma unroll
    for (int s = 0; s < SPLITS; s++) {
        num += g_num[(size_t)s * NT * OUT_FEAT + idx];
        den += g_den[(size_t)s * NT + i];
    }
    den = fmaxf(den, 1e-30f);
    float v = num / den;
    out[idx] = v > 0.f ? v : expm1f(v);
}

// =========================================================================
extern "C" void kernel_launch(void* const* d_in, const int* in_sizes, int n_in,
                              void* d_out, int out_size) {
    const float* x   = (const float*)d_in[0];
    const int*   adj = (const int*)d_in[1];
    const float* W   = (const float*)d_in[2];
    const float* a   = (const float*)d_in[3];
    float* out = (float*)d_out;

    prep_kernel<<<NT / 8, 256>>>(x, W, a);
    attn_kernel<<<dim3(64, SPLITS), 256>>>(adj);
    finalize_kernel<<<(NT * OUT_FEAT) / 256, 256>>>(out);
}

// round 6
// speedup vs baseline: 1.2706x; 1.2706x over previous
#include <cuda_runtime.h>
#include <cuda_fp16.h>
#include <cstdint>
#include <cstddef>

// ============================================================
// GAT attention head, N=8192, IN_F=128, OUT_F=64
//  h = X@W ; e = LeakyReLU(fs_i + fd_j) masked by adj ; softmax ; P@h ; elu
//
// exp(LR(fs+fd)) = max(E_i*E_j, G_i*G_j), E=exp(f), G=exp(0.2f)
// -> no transcendental in the N^2 loop. Fixed-max softmax (logits bounded)
// -> single pass; fp16 P/h via mma.sync.m16n8k16, fp32 accum + denominators.
//
// j-permutation: contraction index k of the MMA maps to j via
//   sigma: k = 2q+(t&1)+8*(t>>1)  <->  j_local = 4q+t
// so each lane's 4 A-fragment j's are contiguous -> adj via one LDG.128/row.
// H smem tiles are stored pre-permuted; B-fragment LDS addressing unchanged.
// ============================================================

#define NT 8192
#define IN_FEAT 128
#define OUT_FEAT 64
#define SPLITS 8
#define JSPAN (NT / SPLITS)      // 1024
#define JTILE 128
#define NTILES (JSPAN / JTILE)   // 8
#define HROW 272                 // padded smem row stride (bytes)

// ---------------- scratch (static device arrays; no allocation) ----------
__device__ __half g_ht[OUT_FEAT * NT];          // h transposed fp16: [f][j]
__device__ float2 g_EGs[NT];                    // (exp(fsrc), exp(0.2 fsrc))
__device__ float2 g_EGd[NT];                    // (exp(fdst), exp(0.2 fdst))
__device__ float  g_num[SPLITS * NT * OUT_FEAT];// partial numerators
__device__ float  g_den[SPLITS * NT];           // partial denominators

// =========================================================================
// Kernel 1: h = X@W ; EG tables ; h^T fp16. Warp owns 4 rows, k-vectorized.
// 256 blocks x 256 threads (32 rows/block).
// =========================================================================
__global__ void __launch_bounds__(256) prep_kernel(const float* __restrict__ x,
                                                   const float* __restrict__ W,
                                                   const float* __restrict__ a) {
    __shared__ float Ws[IN_FEAT * OUT_FEAT];  // 32 KB
    __shared__ float xs[32 * IN_FEAT];        // 16 KB
    int tid = threadIdx.x;
    int i0 = blockIdx.x * 32;

    {   // cooperative loads (float4)
        const float4* W4 = (const float4*)W;
        float4* Ws4 = (float4*)Ws;
#pragma unroll
        for (int u = 0; u < 8; u++) Ws4[tid + u * 256] = W4[tid + u * 256];
        const float4* x4 = (const float4*)(x + (size_t)i0 * IN_FEAT);
        float4* xs4 = (float4*)xs;
#pragma unroll
        for (int u = 0; u < 4; u++) xs4[tid + u * 256] = x4[tid + u * 256];
    }
    __syncthreads();

    int w = tid >> 5, l = tid & 31;
    float acc[4][2];
#pragma unroll
    for (int rr = 0; rr < 4; rr++) { acc[rr][0] = 0.f; acc[rr][1] = 0.f; }

#pragma unroll 4
    for (int k4 = 0; k4 < IN_FEAT; k4 += 4) {
        float4 xv[4];
#pragma unroll
        for (int rr = 0; rr < 4; rr++)
            xv[rr] = *(const float4*)&xs[(w * 4 + rr) * IN_FEAT + k4];
        float2 wv[4];
#pragma unroll
        for (int kk = 0; kk < 4; kk++)
            wv[kk] = *(const float2*)&Ws[(k4 + kk) * OUT_FEAT + 2 * l];
#pragma unroll
        for (int rr = 0; rr < 4; rr++) {
            acc[rr][0] = fmaf(xv[rr].x, wv[0].x, acc[rr][0]);
            acc[rr][1] = fmaf(xv[rr].x, wv[0].y, acc[rr][1]);
            acc[rr][0] = fmaf(xv[rr].y, wv[1].x, acc[rr][0]);
            acc[rr][1] = fmaf(xv[rr].y, wv[1].y, acc[rr][1]);
            acc[rr][0] = fmaf(xv[rr].z, wv[2].x, acc[rr][0]);
            acc[rr][1] = fmaf(xv[rr].z, wv[2].y, acc[rr][1]);
            acc[rr][0] = fmaf(xv[rr].w, wv[3].x, acc[rr][0]);
            acc[rr][1] = fmaf(xv[rr].w, wv[3].y, acc[rr][1]);
        }
    }

    // h^T fp16 stores
#pragma unroll
    for (int rr = 0; rr < 4; rr++) {
        int i = i0 + w * 4 + rr;
        g_ht[(size_t)(2 * l) * NT + i]     = __float2half(acc[rr][0]);
        g_ht[(size_t)(2 * l + 1) * NT + i] = __float2half(acc[rr][1]);
    }

    float a0 = a[2 * l], a1 = a[2 * l + 1];
    float a2 = a[OUT_FEAT + 2 * l], a3 = a[OUT_FEAT + 2 * l + 1];
#pragma unroll
    for (int rr = 0; rr < 4; rr++) {
        float s = acc[rr][0] * a0 + acc[rr][1] * a1;
        float d = acc[rr][0] * a2 + acc[rr][1] * a3;
#pragma unroll
        for (int off = 16; off; off >>= 1) {
            s += __shfl_xor_sync(0xFFFFFFFFu, s, off);
            d += __shfl_xor_sync(0xFFFFFFFFu, d, off);
        }
        if (l == 0) {
            int i = i0 + w * 4 + rr;
            g_EGs[i] = make_float2(expf(s), expf(0.2f * s));
            g_EGd[i] = make_float2(expf(d), expf(0.2f * d));
        }
    }
}

// =========================================================================
// Kernel 2: fused masked-softmax attention (HMMA, j-permuted contraction)
// grid (64 row-blocks, SPLITS j-splits) = 512 CTAs, 256 threads, 2 CTAs/SM.
// =========================================================================
__device__ __forceinline__ void mma16816(float* d, uint32_t a0, uint32_t a1,
                                         uint32_t a2, uint32_t a3,
                                         uint32_t b0, uint32_t b1) {
    asm volatile(
        "mma.sync.aligned.m16n8k16.row.col.f32.f16.f16.f32 "
        "{%0,%1,%2,%3}, {%4,%5,%6,%7}, {%8,%9}, {%0,%1,%2,%3};"
        : "+f"(d[0]), "+f"(d[1]), "+f"(d[2]), "+f"(d[3])
        : "r"(a0), "r"(a1), "r"(a2), "r"(a3), "r"(b0), "r"(b1));
}

__device__ __forceinline__ uint32_t packh2(float x, float y) {
    __half2 h = __floats2half2_rn(x, y);
    return *reinterpret_cast<uint32_t*>(&h);
}

__global__ void __launch_bounds__(256, 2) attn_kernel(const int* __restrict__ adj) {
    __shared__ __align__(16) char  hbuf[2][OUT_FEAT * HROW];  // 2 x 17408 B
    __shared__ __align__(16) float2 egbuf[2][JTILE];           // 2 x 1 KB

    int tid = threadIdx.x, w = tid >> 5, lane = tid & 31;
    int r = lane >> 2, q = lane & 3;
    int i0 = blockIdx.x * 128;
    int split = blockIdx.y;
    int jbase = split * JSPAN;

    int R0 = i0 + w * 16 + r;
    float2 egs0 = g_EGs[R0];
    float2 egs1 = g_EGs[R0 + 8];

    float acc[8][4];
#pragma unroll
    for (int nt = 0; nt < 8; nt++)
#pragma unroll
        for (int v = 0; v < 4; v++) acc[nt][v] = 0.f;
    float ds0 = 0.f, ds1 = 0.f;

    // H staging mapping: idx -> (f = idx>>4, c = idx&15); 16B (8 j) per thread.
    int hf[4], hc[4];
#pragma unroll
    for (int u = 0; u < 4; u++) { int idx = tid + u * 256; hf[u] = idx >> 4; hc[u] = idx & 15; }

    uint4 hreg[4];
    float2 egr;

    // permuted smem store of one 16B H chunk (8 consecutive j)
    auto stage_h = [&](int nb) {
#pragma unroll
        for (int u = 0; u < 4; u++) {
            int blk = hc[u] >> 1, half = hc[u] & 1;
            uint32_t* wp = (uint32_t*)&hbuf[nb][hf[u] * HROW + blk * 32];
            const uint32_t* src = (const uint32_t*)&hreg[u];
            wp[half * 2 + 0] = src[0];   // (m=4q..) -> word q
            wp[half * 2 + 4] = src[1];   // -> word q+4
            wp[half * 2 + 1] = src[2];
            wp[half * 2 + 5] = src[3];
        }
    };

    // preload tile 0
    {
        int jn = jbase;
#pragma unroll
        for (int u = 0; u < 4; u++)
            hreg[u] = *(const uint4*)&g_ht[(size_t)hf[u] * NT + jn + hc[u] * 8];
        if (tid < JTILE) egr = g_EGd[jn + tid];
        stage_h(0);
        if (tid < JTILE) egbuf[0][tid] = egr;
    }
    __syncthreads();

    const size_t rowA = (size_t)R0 * NT;
    const size_t rowB = (size_t)(R0 + 8) * NT;

    for (int t = 0; t < NTILES; t++) {
        int b = t & 1;
        bool more = (t + 1 < NTILES);
        if (more) {
            int jn = jbase + (t + 1) * JTILE;
#pragma unroll
            for (int u = 0; u < 4; u++)
                hreg[u] = *(const uint4*)&g_ht[(size_t)hf[u] * NT + jn + hc[u] * 8];
            if (tid < JTILE) egr = g_EGd[jn + tid];
        }
        const char* hb = hbuf[b];
        const float2* eb = egbuf[b];
        int Jt = jbase + t * JTILE;

#pragma unroll
        for (int kk = 0; kk < 8; kk++) {
            int jloc = kk * 16 + 4 * q;                 // this lane's 4 contiguous j
            int4 avA = *(const int4*)&adj[rowA + Jt + jloc];
            int4 avB = *(const int4*)&adj[rowB + Jt + jloc];
            float4 egA = *(const float4*)&eb[jloc];     // E,G for j, j+1
            float4 egB = *(const float4*)&eb[jloc + 2]; // E,G for j+2, j+3

            float p00 = avA.x ? fmaxf(egs0.x * egA.x, egs0.y * egA.y) : 0.f;
            float p01 = avA.y ? fmaxf(egs0.x * egA.z, egs0.y * egA.w) : 0.f;
            float p02 = avA.z ? fmaxf(egs0.x * egB.x, egs0.y * egB.y) : 0.f;
            float p03 = avA.w ? fmaxf(egs0.x * egB.z, egs0.y * egB.w) : 0.f;
            float p10 = avB.x ? fmaxf(egs1.x * egA.x, egs1.y * egA.y) : 0.f;
            float p11 = avB.y ? fmaxf(egs1.x * egA.z, egs1.y * egA.w) : 0.f;
            float p12 = avB.z ? fmaxf(egs1.x * egB.x, egs1.y * egB.y) : 0.f;
            float p13 = avB.w ? fmaxf(egs1.x * egB.z, egs1.y * egB.w) : 0.f;

            ds0 += (p00 + p01) + (p02 + p03);
            ds1 += (p10 + p11) + (p12 + p13);

            // A-frag under sigma: a0=(k=2q,2q+1)->j=4q,4q+1 ; a2=(k=2q+8,2q+9)->j=4q+2,4q+3
            uint32_t A0 = packh2(p00, p01);
            uint32_t A1 = packh2(p10, p11);
            uint32_t A2 = packh2(p02, p03);
            uint32_t A3 = packh2(p12, p13);

            int ko = kk * 32 + q * 4;   // B-frag addressing unchanged (slot space)
#pragma unroll
            for (int nt = 0; nt < 8; nt++) {
                const char* base = hb + (nt * 8 + r) * HROW;
                uint32_t b0 = *(const uint32_t*)(base + ko);
                uint32_t b1 = *(const uint32_t*)(base + ko + 16);
                mma16816(acc[nt], A0, A1, A2, A3, b0, b1);
            }
        }

        if (more) {
            stage_h(b ^ 1);
            if (tid < JTILE) egbuf[b ^ 1][tid] = egr;
        }
        __syncthreads();
    }

    // denominator: reduce over the 4 lanes (q) sharing a row
    ds0 += __shfl_xor_sync(0xFFFFFFFFu, ds0, 1);
    ds0 += __shfl_xor_sync(0xFFFFFFFFu, ds0, 2);
    ds1 += __shfl_xor_sync(0xFFFFFFFFu, ds1, 1);
    ds1 += __shfl_xor_sync(0xFFFFFFFFu, ds1, 2);
    if (q == 0) {
        g_den[(size_t)split * NT + R0]     = ds0;
        g_den[(size_t)split * NT + R0 + 8] = ds1;
    }

    // numerators -> gmem partials
    float* gn = &g_num[(size_t)split * NT * OUT_FEAT];
#pragma unroll
    for (int nt = 0; nt < 8; nt++) {
        int col = nt * 8 + q * 2;
        *(float2*)&gn[(size_t)R0 * OUT_FEAT + col]       = make_float2(acc[nt][0], acc[nt][1]);
        *(float2*)&gn[(size_t)(R0 + 8) * OUT_FEAT + col] = make_float2(acc[nt][2], acc[nt][3]);
    }
}

// =========================================================================
// Kernel 3: combine split partials, divide, elu
// =========================================================================
__global__ void __launch_bounds__(256) finalize_kernel(float* __restrict__ out) {
    size_t idx = (size_t)blockIdx.x * 256 + threadIdx.x;
    size_t i = idx >> 6;
    float num = 0.f, den = 0.f;
#pragma unroll
    for (int s = 0; s < SPLITS; s++) {
        num += g_num[(size_t)s * NT * OUT_FEAT + idx];
        den += g_den[(size_t)s * NT + i];
    }
    den = fmaxf(den, 1e-30f);
    float v = num / den;
    out[idx] = v > 0.f ? v : expm1f(v);
}

// =========================================================================
extern "C" void kernel_launch(void* const* d_in, const int* in_sizes, int n_in,
                              void* d_out, int out_size) {
    const float* x   = (const float*)d_in[0];
    const int*   adj = (const int*)d_in[1];
    const float* W   = (const float*)d_in[2];
    const float* a   = (const float*)d_in[3];
    float* out = (float*)d_out;

    prep_kernel<<<NT / 32, 256>>>(x, W, a);
    attn_kernel<<<dim3(64, SPLITS), 256>>>(adj);
    finalize_kernel<<<(NT * OUT_FEAT) / 256, 256>>>(out);
}